// round 16
// baseline (speedup 1.0000x reference)
#include <cuda_runtime.h>
#include <cuda_fp16.h>
#include <cstdint>

// ======================= problem constants =======================
#define BN 4096
#define DK 512
#define NTOT 1056                 // lower-tri 128x64 tiles: 32^2 + 32

#define MARGINF 0.6f
#define LOF     0.56f
#define HIF     0.64f
#define M2F     (MARGINF * MARGINF)       // 0.36
#define LO2F    (LOF * LOF)               // 0.3136
#define HI2F    (HIF * HIF)               // 0.4096

// ======================= device state ===========================
__device__ __half         g_xh[(size_t)BN * DK];     // 4 MB fp16 copy of X
__device__ float          g_norms[BN];               // exact fp32 squared norms
__device__ float          g_buf[(size_t)BN * BN];    // compact neg d<HI values
__device__ double         g_pos_loss;
__device__ double         g_negsum;
__device__ unsigned int   g_right;
__device__ unsigned int   g_m;
__device__ unsigned int   g_k;
__device__ unsigned int   g_done;

// ======================= PTX helpers =============================
__device__ __forceinline__ uint32_t smem_to_u32(const void* p) {
    uint32_t a;
    asm("{ .reg .u64 t; cvta.to.shared.u64 t, %1; cvt.u32.u64 %0, t; }" : "=r"(a) : "l"(p));
    return a;
}
__device__ __forceinline__ void cp16(uint32_t dst, const void* src) {
    asm volatile("cp.async.cg.shared.global [%0], [%1], 16;" :: "r"(dst), "l"(src));
}
#define CP_COMMIT() asm volatile("cp.async.commit_group;" ::: "memory")
#define CP_WAIT(n)  asm volatile("cp.async.wait_group %0;" :: "n"(n) : "memory")

#define LDSM_X4(r, addr) \
    asm volatile("ldmatrix.sync.aligned.m8n8.x4.shared.b16 {%0,%1,%2,%3}, [%4];" \
                 : "=r"((r)[0]), "=r"((r)[1]), "=r"((r)[2]), "=r"((r)[3]) : "r"(addr))

// fp16 inputs, fp16 accumulate: c = {c01, c23} as two f16x2 regs
__device__ __forceinline__ void mma16816h(uint32_t* c, const uint32_t* a,
                                          uint32_t b0, uint32_t b1) {
    asm volatile(
        "mma.sync.aligned.m16n8k16.row.col.f16.f16.f16.f16 "
        "{%0,%1}, {%2,%3,%4,%5}, {%6,%7}, {%0,%1};"
        : "+r"(c[0]), "+r"(c[1])
        : "r"(a[0]), "r"(a[1]), "r"(a[2]), "r"(a[3]), "r"(b0), "r"(b1));
}

#define SWZ(off) ((off) ^ (((off) >> 3) & 0x70))

// ======================= K1: fp16 convert + norms + labels ==============
__global__ void prep_kernel(const float* __restrict__ X, const int* __restrict__ tgt) {
    if (blockIdx.x == BN / 8) {
        __shared__ unsigned cnt[64];
        int tid = threadIdx.x;
        if (tid < 64) cnt[tid] = 0u;
        __syncthreads();
        for (int i = tid; i < BN; i += blockDim.x) atomicAdd(&cnt[tgt[i] & 63], 1u);
        __syncthreads();
        if (tid == 0) {
            unsigned long long np = 0;
            for (int c = 0; c < 64; ++c) np += (unsigned long long)cnt[c] * cnt[c];
            g_k        = (unsigned)((np - (unsigned long long)BN) / 2ull);
            g_pos_loss = 0.0;
            g_negsum   = 0.0;
            g_right    = 0u;
            g_m        = 0u;
            g_done     = 0u;
        }
        return;
    }
    int row  = blockIdx.x * 8 + (threadIdx.x >> 5);
    int lane = threadIdx.x & 31;
    const float* xr = X + (size_t)row * DK;
    float s = 0.0f;
#pragma unroll
    for (int i = 0; i < 4; ++i) {
        float4 v = *(const float4*)(xr + 4 * lane + 128 * i);
        s += v.x * v.x + v.y * v.y + v.z * v.z + v.w * v.w;
        __half2 p0 = __floats2half2_rn(v.x, v.y);
        __half2 p1 = __floats2half2_rn(v.z, v.w);
        *(__half2*)(g_xh + (size_t)row * DK + 4 * lane + 128 * i)     = p0;
        *(__half2*)(g_xh + (size_t)row * DK + 4 * lane + 128 * i + 2) = p1;
    }
#pragma unroll
    for (int o = 16; o; o >>= 1) s += __shfl_down_sync(0xffffffffu, s, o);
    if (lane == 0) g_norms[row] = s;
}

// ======================= K2: fused GEMM + stats + finalize ==============
// r13 configuration (proven optimum): 128(M)x64(N) tile/CTA, 8 warps
// (4M x 2N), warp tile 32x32 fp16-acc, 3 CTAs/SM, 3-stage cp.async ring,
// 1 barrier/chunk, fragment double-buffering, hoisted swizzled addresses.
// This round: kc loop FULLY UNROLLED (static ring-stage offsets).
#define SM_SCN  0
#define SM_SCT  256
#define SM_SRN  512
#define SM_SRT  1024
#define SM_RED  1536
#define SM_TILE 2048
#define STAGE_BYTES 24576
#define SM_TOTAL (SM_TILE + 3 * STAGE_BYTES)

__device__ __forceinline__ void stage_load(uint32_t sbase, int r0, int c0, int kc, int tid) {
    uint32_t base = sbase + SM_TILE + (uint32_t)(kc % 3) * STAGE_BYTES;
    // A: 128 rows x 128B; 2 threads per row, 64B each
    {
        int row = tid >> 1, half = tid & 1;
        const char* src = (const char*)(g_xh + (size_t)(r0 + row) * DK + kc * 64 + half * 32);
#pragma unroll
        for (int i = 0; i < 4; ++i)
            cp16(base + SWZ((uint32_t)row * 128u + (uint32_t)half * 64u + (uint32_t)i * 16u),
                 src + i * 16);
    }
    // B: 64 rows x 128B; 4 threads per row, 32B each
    {
        int row = tid >> 2, q = tid & 3;
        const char* src = (const char*)(g_xh + (size_t)(c0 + row) * DK + kc * 64 + q * 16);
        uint32_t bb = base + 16384u;
#pragma unroll
        for (int i = 0; i < 2; ++i)
            cp16(bb + SWZ((uint32_t)row * 128u + (uint32_t)q * 32u + (uint32_t)i * 16u),
                 src + i * 16);
    }
}

__global__ void __launch_bounds__(256, 3) gemm_stats_kernel(const int* __restrict__ tgt,
                                                            float* __restrict__ out,
                                                            int out_size) {
    extern __shared__ char smem[];
    const uint32_t sbase = smem_to_u32(smem);
    const int tid  = threadIdx.x;
    const int wid  = tid >> 5;
    const int lane = tid & 31;

    // decode tile: cumulative tiles up to by = by^2 + by; bx in [0, 2*by+1]
    int t = blockIdx.x;
    int by = 0;
    while ((by + 1) * (by + 2) <= t) ++by;
    int bx = t - by * (by + 1);
    const int r0 = by * 128, c0 = bx * 64;
    const bool bnd = (bx >= 2 * by);     // contains diagonal / above-diag elems

    if (tid < 128) {
        ((float*)(smem + SM_SRN))[tid] = g_norms[r0 + tid];
        ((int*)(smem + SM_SRT))[tid]   = tgt[r0 + tid];
    } else if (tid < 192) {
        int u = tid - 128;
        ((float*)(smem + SM_SCN))[u] = g_norms[c0 + u];
        ((int*)(smem + SM_SCT))[u]   = tgt[c0 + u];
    }

    const int wm = wid & 3;   // rows wm*32
    const int wn = wid >> 2;  // cols wn*32

    // hoisted swizzled frag offsets (ks=0); per-ks addr = off ^ (ks<<5)
    uint32_t aoff[2], boff[2];
#pragma unroll
    for (int mi = 0; mi < 2; ++mi)
        aoff[mi] = SWZ((uint32_t)(wm * 32 + mi * 16 + (lane & 15)) * 128u +
                       (uint32_t)(lane >> 4) * 16u);
#pragma unroll
    for (int nt = 0; nt < 2; ++nt)
        boff[nt] = SWZ((uint32_t)(wn * 32 + nt * 16 + (lane & 15)) * 128u +
                       (uint32_t)(lane >> 4) * 16u) + 16384u;

    // fp16 accumulators: [mi][ni][rh] = f16x2 (rl=0 lo, rl=1 hi)
    uint32_t acc[2][4][2];
#pragma unroll
    for (int mi = 0; mi < 2; ++mi)
#pragma unroll
        for (int ni = 0; ni < 4; ++ni) { acc[mi][ni][0] = 0u; acc[mi][ni][1] = 0u; }

    stage_load(sbase, r0, c0, 0, tid); CP_COMMIT();
    stage_load(sbase, r0, c0, 1, tid); CP_COMMIT();

    uint32_t a[2][2][4], b[2][2][4];   // [buf][frag][regs]

#pragma unroll
    for (int kc = 0; kc < 8; ++kc) {
        if (kc < 7) CP_WAIT(1); else CP_WAIT(0);
        __syncthreads();   // single barrier per chunk (3-stage ring makes it safe)

        uint32_t tbase = sbase + SM_TILE + (uint32_t)(kc % 3) * STAGE_BYTES;

        // prime fragments for ks = 0
#pragma unroll
        for (int mi = 0; mi < 2; ++mi) LDSM_X4(a[0][mi], tbase + aoff[mi]);
#pragma unroll
        for (int nt = 0; nt < 2; ++nt) LDSM_X4(b[0][nt], tbase + boff[nt]);

#pragma unroll
        for (int ks = 0; ks < 4; ++ks) {
            const int cur = ks & 1, nxt = cur ^ 1;
            if (ks < 3) {
                uint32_t kx = (uint32_t)(ks + 1) << 5;
#pragma unroll
                for (int mi = 0; mi < 2; ++mi) LDSM_X4(a[nxt][mi], tbase + (aoff[mi] ^ kx));
#pragma unroll
                for (int nt = 0; nt < 2; ++nt) LDSM_X4(b[nxt][nt], tbase + (boff[nt] ^ kx));
            }
#pragma unroll
            for (int mi = 0; mi < 2; ++mi)
#pragma unroll
                for (int ni = 0; ni < 4; ++ni) {
                    int nt = ni >> 1, hi = ni & 1;
                    mma16816h(acc[mi][ni], a[cur][mi], b[cur][nt][hi], b[cur][nt][hi + 2]);
                }
        }
        if (kc < 6) { stage_load(sbase, r0, c0, kc + 2, tid); CP_COMMIT(); }
    }

    // -------- single-pass epilogue (squared-distance domain) --------
    const float* scn = (const float*)(smem + SM_SCN);
    const int*   sct = (const int*)(smem + SM_SCT);
    const float* srn = (const float*)(smem + SM_SRN);
    const int*   srt = (const int*)(smem + SM_SRT);

    float pl = 0.0f, ns = 0.0f;
    unsigned rightw = 0u;

    if (!bnd) {
        // pure below-diagonal tile: uniform weight 2
        unsigned right = 0u;
#pragma unroll
        for (int mi = 0; mi < 2; ++mi) {
#pragma unroll
            for (int rh = 0; rh < 2; ++rh) {
                const int il = wm * 32 + mi * 16 + (lane >> 2) + rh * 8;
                const float nr = srn[il];
                const int   tr = srt[il];
#pragma unroll
                for (int ni = 0; ni < 4; ++ni) {
                    const int jb = wn * 32 + ni * 8 + ((lane & 3) << 1);
                    const float2 cn = *(const float2*)(scn + jb);
                    const int2   ct = *(const int2*)(sct + jb);
                    const float2 g2 = __half22float2(*(const __half2*)&acc[mi][ni][rh]);
#pragma unroll
                    for (int rl = 0; rl < 2; ++rl) {
                        float g  = rl ? g2.y : g2.x;
                        float sq = nr + fmaf(-2.0f, g, rl ? cn.y : cn.x);
                        bool pos   = (tr == (rl ? ct.y : ct.x));
                        bool small = (sq < M2F);
                        right += (pos == small) ? 1u : 0u;
                        if (pos) {
                            if (sq > LO2F) pl += sqrtf(sq) - LOF;
                        } else if (sq < HI2F) {                // ~never taken
                            float d = sqrtf(fmaxf(sq, 0.0f));
                            ns += HIF - d;
                            unsigned idx = atomicAdd(&g_m, 2u);
                            g_buf[idx] = d; g_buf[idx + 1] = d;
                        }
                    }
                }
            }
        }
        pl *= 2.0f; ns *= 2.0f; rightw = right * 2u;
    } else {
        // boundary tile: per-element weight {0,1,2}, exact diagonal
#pragma unroll
        for (int mi = 0; mi < 2; ++mi) {
#pragma unroll
            for (int rh = 0; rh < 2; ++rh) {
                const int il = wm * 32 + mi * 16 + (lane >> 2) + rh * 8;
                const int i_g = r0 + il;
                const float nr = srn[il];
                const int   tr = srt[il];
#pragma unroll
                for (int ni = 0; ni < 4; ++ni) {
                    const int jb = wn * 32 + ni * 8 + ((lane & 3) << 1);
                    const float2 cn = *(const float2*)(scn + jb);
                    const int2   ct = *(const int2*)(sct + jb);
                    const float2 g2 = __half22float2(*(const __half2*)&acc[mi][ni][rh]);
#pragma unroll
                    for (int rl = 0; rl < 2; ++rl) {
                        const int j_g = c0 + jb + rl;
                        if (i_g < j_g) continue;               // weight 0
                        unsigned uw = (i_g == j_g) ? 1u : 2u;
                        float g  = rl ? g2.y : g2.x;
                        float sq = nr + fmaf(-2.0f, g, rl ? cn.y : cn.x);
                        if (i_g == j_g) sq = 0.0f;             // exact diagonal
                        bool pos   = (tr == (rl ? ct.y : ct.x));
                        bool small = (sq < M2F);
                        rightw += (pos == small) ? uw : 0u;
                        if (pos) {
                            if (sq > LO2F) pl += (float)uw * (sqrtf(sq) - LOF);
                        } else if (sq < HI2F) {
                            float d = sqrtf(fmaxf(sq, 0.0f));
                            ns += (float)uw * (HIF - d);
                            unsigned idx = atomicAdd(&g_m, uw);
                            g_buf[idx] = d;
                            if (uw == 2u) g_buf[idx + 1] = d;
                        }
                    }
                }
            }
        }
    }

    // block reduce -> global atomics
#pragma unroll
    for (int o = 16; o; o >>= 1) {
        pl     += __shfl_down_sync(0xffffffffu, pl, o);
        ns     += __shfl_down_sync(0xffffffffu, ns, o);
        rightw += __shfl_down_sync(0xffffffffu, rightw, o);
    }
    float*    rpl = (float*)(smem + SM_RED);
    float*    rns = (float*)(smem + SM_RED + 32);
    unsigned* rrt = (unsigned*)(smem + SM_RED + 64);
    if (lane == 0) { rpl[wid] = pl; rns[wid] = ns; rrt[wid] = rightw; }
    __syncthreads();
    if (tid == 0) {
        float plb = 0.0f, nsb = 0.0f; unsigned rb = 0u;
#pragma unroll
        for (int w = 0; w < 8; ++w) { plb += rpl[w]; nsb += rns[w]; rb += rrt[w]; }
        atomicAdd(&g_pos_loss, (double)plb);
        atomicAdd(&g_negsum, (double)nsb);
        atomicAdd(&g_right, rb);
    }

    // ---------------- last-block finalize ----------------
    __shared__ unsigned s_last;
    if (tid == 0) {
        __threadfence();
        unsigned prev = atomicAdd(&g_done, 1u);
        s_last = (prev == NTOT - 1) ? 1u : 0u;
    }
    __syncthreads();
    if (!s_last) return;

    unsigned* hist = (unsigned*)(smem + SM_TILE);   // reuse tile smem
    __shared__ unsigned sh_b0, sh_b1, sh_b2, sh_r;
    __shared__ double   rsm[8];
    __shared__ double   sh_negloss;

    const unsigned k = atomicAdd(&g_k, 0u);
    const unsigned m = atomicAdd(&g_m, 0u);
    const int nt = 256;
    double negloss;

    if (m > k) {
        for (int bb = tid; bb < 2048; bb += nt) hist[bb] = 0u;
        __syncthreads();
        for (unsigned idx = tid; idx < m; idx += nt)
            atomicAdd(&hist[__float_as_uint(g_buf[idx]) >> 21], 1u);
        __syncthreads();
        if (tid == 0) {
            unsigned r = k; int bb = 0;
            for (; bb < 2048; ++bb) { if (r < hist[bb]) break; r -= hist[bb]; }
            sh_b0 = (unsigned)bb; sh_r = r;
        }
        __syncthreads();
        unsigned b0 = sh_b0;
        for (int bb = tid; bb < 2048; bb += nt) hist[bb] = 0u;
        __syncthreads();
        for (unsigned idx = tid; idx < m; idx += nt) {
            unsigned key = __float_as_uint(g_buf[idx]);
            if ((key >> 21) == b0) atomicAdd(&hist[(key >> 10) & 2047u], 1u);
        }
        __syncthreads();
        if (tid == 0) {
            unsigned r = sh_r; int bb = 0;
            for (; bb < 2048; ++bb) { if (r < hist[bb]) break; r -= hist[bb]; }
            sh_b1 = (unsigned)bb; sh_r = r;
        }
        __syncthreads();
        unsigned pref = (b0 << 11) | sh_b1;
        for (int bb = tid; bb < 1024; bb += nt) hist[bb] = 0u;
        __syncthreads();
        for (unsigned idx = tid; idx < m; idx += nt) {
            unsigned key = __float_as_uint(g_buf[idx]);
            if ((key >> 10) == pref) atomicAdd(&hist[key & 1023u], 1u);
        }
        __syncthreads();
        if (tid == 0) {
            unsigned r = sh_r; int bb = 0;
            for (; bb < 1024; ++bb) { if (r < hist[bb]) break; r -= hist[bb]; }
            sh_b2 = (unsigned)bb;
        }
        __syncthreads();
        unsigned thr_key = (sh_b0 << 21) | (sh_b1 << 10) | sh_b2;
        double a2 = 0.0;
        for (unsigned idx = tid; idx < m; idx += nt) {
            float v = g_buf[idx];
            if (__float_as_uint(v) < thr_key) a2 += (double)(HIF - v);
        }
#pragma unroll
        for (int o = 16; o; o >>= 1) a2 += __shfl_down_sync(0xffffffffu, a2, o);
        if (lane == 0) rsm[wid] = a2;
        __syncthreads();
        if (tid == 0) {
            double s = 0.0;
            for (int w = 0; w < 8; ++w) s += rsm[w];
            sh_negloss = s;
        }
        __syncthreads();
        negloss = sh_negloss;
    } else {
        negloss = g_negsum;
    }

    if (tid == 0) {
        double loss = (g_pos_loss + negloss) / (2.0 * (double)k);
        double accy = (double)atomicAdd(&g_right, 0u) / ((double)BN * (double)BN);
        out[0] = (float)loss;
        if (out_size > 1) out[1] = (float)accy;
    }
}

// ======================= launch ========================================
extern "C" void kernel_launch(void* const* d_in, const int* in_sizes, int n_in,
                              void* d_out, int out_size) {
    (void)in_sizes; (void)n_in;
    const float* X   = (const float*)d_in[0];
    const int*   tgt = (const int*)d_in[1];
    float*       out = (float*)d_out;

    cudaFuncSetAttribute(gemm_stats_kernel,
                         cudaFuncAttributeMaxDynamicSharedMemorySize, SM_TOTAL);

    prep_kernel<<<BN / 8 + 1, 256>>>(X, tgt);
    gemm_stats_kernel<<<NTOT, 256, SM_TOTAL>>>(tgt, out, out_size);
}

// round 17
// speedup vs baseline: 1.0387x; 1.0387x over previous
#include <cuda_runtime.h>
#include <cuda_fp16.h>
#include <cstdint>

// ======================= problem constants =======================
#define BN 4096
#define DK 512
#define NTOT 1056                 // lower-tri 128x64 tiles: 32^2 + 32

#define MARGINF 0.6f
#define LOF     0.56f
#define HIF     0.64f
#define M2F     (MARGINF * MARGINF)       // 0.36
#define LO2F    (LOF * LOF)               // 0.3136
#define HI2F    (HIF * HIF)               // 0.4096

// ======================= device state ===========================
__device__ __half         g_xh[(size_t)BN * DK];     // 4 MB fp16 copy of X
__device__ float          g_norms[BN];               // exact fp32 squared norms
__device__ float          g_buf[(size_t)BN * BN];    // compact neg d<HI values
__device__ double         g_pos_loss;
__device__ double         g_negsum;
__device__ unsigned int   g_right;
__device__ unsigned int   g_m;
__device__ unsigned int   g_k;
__device__ unsigned int   g_done;

// ======================= PTX helpers =============================
__device__ __forceinline__ uint32_t smem_to_u32(const void* p) {
    uint32_t a;
    asm("{ .reg .u64 t; cvta.to.shared.u64 t, %1; cvt.u32.u64 %0, t; }" : "=r"(a) : "l"(p));
    return a;
}
__device__ __forceinline__ void cp16(uint32_t dst, const void* src) {
    asm volatile("cp.async.cg.shared.global [%0], [%1], 16;" :: "r"(dst), "l"(src));
}
#define CP_COMMIT() asm volatile("cp.async.commit_group;" ::: "memory")
#define CP_WAIT(n)  asm volatile("cp.async.wait_group %0;" :: "n"(n) : "memory")

#define LDSM_X4(r, addr) \
    asm volatile("ldmatrix.sync.aligned.m8n8.x4.shared.b16 {%0,%1,%2,%3}, [%4];" \
                 : "=r"((r)[0]), "=r"((r)[1]), "=r"((r)[2]), "=r"((r)[3]) : "r"(addr))

// fp16 inputs, fp16 accumulate: c = {c01, c23} as two f16x2 regs
__device__ __forceinline__ void mma16816h(uint32_t* c, const uint32_t* a,
                                          uint32_t b0, uint32_t b1) {
    asm volatile(
        "mma.sync.aligned.m16n8k16.row.col.f16.f16.f16.f16 "
        "{%0,%1}, {%2,%3,%4,%5}, {%6,%7}, {%0,%1};"
        : "+r"(c[0]), "+r"(c[1])
        : "r"(a[0]), "r"(a[1]), "r"(a[2]), "r"(a[3]), "r"(b0), "r"(b1));
}

#define SWZ(off) ((off) ^ (((off) >> 3) & 0x70))

// ======================= K1: fp16 convert + norms + labels ==============
__global__ void prep_kernel(const float* __restrict__ X, const int* __restrict__ tgt) {
    if (blockIdx.x == BN / 8) {
        __shared__ unsigned cnt[64];
        int tid = threadIdx.x;
        if (tid < 64) cnt[tid] = 0u;
        __syncthreads();
        for (int i = tid; i < BN; i += blockDim.x) atomicAdd(&cnt[tgt[i] & 63], 1u);
        __syncthreads();
        if (tid == 0) {
            unsigned long long np = 0;
            for (int c = 0; c < 64; ++c) np += (unsigned long long)cnt[c] * cnt[c];
            g_k        = (unsigned)((np - (unsigned long long)BN) / 2ull);
            g_pos_loss = 0.0;
            g_negsum   = 0.0;
            g_right    = 0u;
            g_m        = 0u;
            g_done     = 0u;
        }
        return;
    }
    int row  = blockIdx.x * 8 + (threadIdx.x >> 5);
    int lane = threadIdx.x & 31;
    const float* xr = X + (size_t)row * DK;
    float s = 0.0f;
#pragma unroll
    for (int i = 0; i < 4; ++i) {
        float4 v = *(const float4*)(xr + 4 * lane + 128 * i);
        s += v.x * v.x + v.y * v.y + v.z * v.z + v.w * v.w;
        __half2 p0 = __floats2half2_rn(v.x, v.y);
        __half2 p1 = __floats2half2_rn(v.z, v.w);
        *(__half2*)(g_xh + (size_t)row * DK + 4 * lane + 128 * i)     = p0;
        *(__half2*)(g_xh + (size_t)row * DK + 4 * lane + 128 * i + 2) = p1;
    }
#pragma unroll
    for (int o = 16; o; o >>= 1) s += __shfl_down_sync(0xffffffffu, s, o);
    if (lane == 0) g_norms[row] = s;
}

// ======================= K2: fused GEMM + stats + finalize ==============
// r13 skeleton: 128(M)x64(N) tile/CTA, lower-tri tiles, 8 warps (4M x 2N),
// warp tile 32x32, 3 CTAs/SM, 3-stage cp.async ring, 1 barrier/chunk,
// fragment double-buffering with hoisted swizzled addresses.
// fp16 inputs + fp16 accumulators.
#define SM_SCN  0
#define SM_SCT  256
#define SM_SRN  512
#define SM_SRT  1024
#define SM_RED  1536
#define SM_TILE 2048
#define STAGE_BYTES 24576
#define SM_TOTAL (SM_TILE + 3 * STAGE_BYTES)

__device__ __forceinline__ void stage_load(uint32_t sbase, int r0, int c0, int kc, int tid) {
    uint32_t base = sbase + SM_TILE + (uint32_t)(kc % 3) * STAGE_BYTES;
    // A: 128 rows x 128B; 2 threads per row, 64B each
    {
        int row = tid >> 1, half = tid & 1;
        const char* src = (const char*)(g_xh + (size_t)(r0 + row) * DK + kc * 64 + half * 32);
#pragma unroll
        for (int i = 0; i < 4; ++i)
            cp16(base + SWZ((uint32_t)row * 128u + (uint32_t)half * 64u + (uint32_t)i * 16u),
                 src + i * 16);
    }
    // B: 64 rows x 128B; 4 threads per row, 32B each
    {
        int row = tid >> 2, q = tid & 3;
        const char* src = (const char*)(g_xh + (size_t)(c0 + row) * DK + kc * 64 + q * 16);
        uint32_t bb = base + 16384u;
#pragma unroll
        for (int i = 0; i < 2; ++i)
            cp16(bb + SWZ((uint32_t)row * 128u + (uint32_t)q * 32u + (uint32_t)i * 16u),
                 src + i * 16);
    }
}

__global__ void __launch_bounds__(256, 3) gemm_stats_kernel(const int* __restrict__ tgt,
                                                            float* __restrict__ out,
                                                            int out_size) {
    extern __shared__ char smem[];
    const uint32_t sbase = smem_to_u32(smem);
    const int tid  = threadIdx.x;
    const int wid  = tid >> 5;
    const int lane = tid & 31;

    // decode tile: cumulative tiles up to by = by^2 + by; bx in [0, 2*by+1]
    int t = blockIdx.x;
    int by = 0;
    while ((by + 1) * (by + 2) <= t) ++by;
    int bx = t - by * (by + 1);
    const int r0 = by * 128, c0 = bx * 64;
    const bool bnd = (bx >= 2 * by);     // contains diagonal / above-diag elems

    if (tid < 128) {
        ((float*)(smem + SM_SRN))[tid] = g_norms[r0 + tid];
        ((int*)(smem + SM_SRT))[tid]   = tgt[r0 + tid];
    } else if (tid < 192) {
        int u = tid - 128;
        ((float*)(smem + SM_SCN))[u] = g_norms[c0 + u];
        ((int*)(smem + SM_SCT))[u]   = tgt[c0 + u];
    }

    const int wm = wid & 3;   // rows wm*32
    const int wn = wid >> 2;  // cols wn*32

    // hoisted swizzled frag offsets (ks=0); per-ks addr = off ^ (ks<<5)
    uint32_t aoff[2], boff[2];
#pragma unroll
    for (int mi = 0; mi < 2; ++mi)
        aoff[mi] = SWZ((uint32_t)(wm * 32 + mi * 16 + (lane & 15)) * 128u +
                       (uint32_t)(lane >> 4) * 16u);
#pragma unroll
    for (int nt = 0; nt < 2; ++nt)
        boff[nt] = SWZ((uint32_t)(wn * 32 + nt * 16 + (lane & 15)) * 128u +
                       (uint32_t)(lane >> 4) * 16u) + 16384u;

    // fp16 accumulators: [mi][ni][rh] = f16x2 (rl=0 lo, rl=1 hi)
    uint32_t acc[2][4][2];
#pragma unroll
    for (int mi = 0; mi < 2; ++mi)
#pragma unroll
        for (int ni = 0; ni < 4; ++ni) { acc[mi][ni][0] = 0u; acc[mi][ni][1] = 0u; }

    stage_load(sbase, r0, c0, 0, tid); CP_COMMIT();
    stage_load(sbase, r0, c0, 1, tid); CP_COMMIT();

    uint32_t a[2][2][4], b[2][2][4];   // [buf][frag][regs]

    for (int kc = 0; kc < 8; ++kc) {
        if (kc < 7) CP_WAIT(1); else CP_WAIT(0);
        __syncthreads();   // single barrier per chunk (3-stage ring makes it safe)

        uint32_t tbase = sbase + SM_TILE + (uint32_t)(kc % 3) * STAGE_BYTES;

        // prime fragments for ks = 0
#pragma unroll
        for (int mi = 0; mi < 2; ++mi) LDSM_X4(a[0][mi], tbase + aoff[mi]);
#pragma unroll
        for (int nt = 0; nt < 2; ++nt) LDSM_X4(b[0][nt], tbase + boff[nt]);

#pragma unroll
        for (int ks = 0; ks < 4; ++ks) {
            const int cur = ks & 1, nxt = cur ^ 1;
            if (ks < 3) {
                uint32_t kx = (uint32_t)(ks + 1) << 5;
#pragma unroll
                for (int mi = 0; mi < 2; ++mi) LDSM_X4(a[nxt][mi], tbase + (aoff[mi] ^ kx));
#pragma unroll
                for (int nt = 0; nt < 2; ++nt) LDSM_X4(b[nxt][nt], tbase + (boff[nt] ^ kx));
            }
#pragma unroll
            for (int mi = 0; mi < 2; ++mi)
#pragma unroll
                for (int ni = 0; ni < 4; ++ni) {
                    int nt = ni >> 1, hi = ni & 1;
                    mma16816h(acc[mi][ni], a[cur][mi], b[cur][nt][hi], b[cur][nt][hi + 2]);
                }
        }
        if (kc < 6) { stage_load(sbase, r0, c0, kc + 2, tid); CP_COMMIT(); }
    }

    // -------- single-pass epilogue (squared-distance domain) --------
    const float* scn = (const float*)(smem + SM_SCN);
    const int*   sct = (const int*)(smem + SM_SCT);
    const float* srn = (const float*)(smem + SM_SRN);
    const int*   srt = (const int*)(smem + SM_SRT);

    float pl = 0.0f, ns = 0.0f;
    unsigned rightw = 0u;

    if (!bnd) {
        // pure below-diagonal tile: uniform weight 2
        unsigned right = 0u;
#pragma unroll
        for (int mi = 0; mi < 2; ++mi) {
#pragma unroll
            for (int rh = 0; rh < 2; ++rh) {
                const int il = wm * 32 + mi * 16 + (lane >> 2) + rh * 8;
                const float nr = srn[il];
                const int   tr = srt[il];
#pragma unroll
                for (int ni = 0; ni < 4; ++ni) {
                    const int jb = wn * 32 + ni * 8 + ((lane & 3) << 1);
                    const float2 cn = *(const float2*)(scn + jb);
                    const int2   ct = *(const int2*)(sct + jb);
                    const float2 g2 = __half22float2(*(const __half2*)&acc[mi][ni][rh]);
#pragma unroll
                    for (int rl = 0; rl < 2; ++rl) {
                        float g  = rl ? g2.y : g2.x;
                        float sq = nr + fmaf(-2.0f, g, rl ? cn.y : cn.x);
                        bool pos   = (tr == (rl ? ct.y : ct.x));
                        bool small = (sq < M2F);
                        right += (pos == small) ? 1u : 0u;
                        if (pos) {
                            if (sq > LO2F) pl += sqrtf(sq) - LOF;
                        } else if (sq < HI2F) {                // ~never taken
                            float d = sqrtf(fmaxf(sq, 0.0f));
                            ns += HIF - d;
                            unsigned idx = atomicAdd(&g_m, 2u);
                            g_buf[idx] = d; g_buf[idx + 1] = d;
                        }
                    }
                }
            }
        }
        pl *= 2.0f; ns *= 2.0f; rightw = right * 2u;
    } else {
        // boundary tile: per-element weight {0,1,2}, exact diagonal
#pragma unroll
        for (int mi = 0; mi < 2; ++mi) {
#pragma unroll
            for (int rh = 0; rh < 2; ++rh) {
                const int il = wm * 32 + mi * 16 + (lane >> 2) + rh * 8;
                const int i_g = r0 + il;
                const float nr = srn[il];
                const int   tr = srt[il];
#pragma unroll
                for (int ni = 0; ni < 4; ++ni) {
                    const int jb = wn * 32 + ni * 8 + ((lane & 3) << 1);
                    const float2 cn = *(const float2*)(scn + jb);
                    const int2   ct = *(const int2*)(sct + jb);
                    const float2 g2 = __half22float2(*(const __half2*)&acc[mi][ni][rh]);
#pragma unroll
                    for (int rl = 0; rl < 2; ++rl) {
                        const int j_g = c0 + jb + rl;
                        if (i_g < j_g) continue;               // weight 0
                        unsigned uw = (i_g == j_g) ? 1u : 2u;
                        float g  = rl ? g2.y : g2.x;
                        float sq = nr + fmaf(-2.0f, g, rl ? cn.y : cn.x);
                        if (i_g == j_g) sq = 0.0f;             // exact diagonal
                        bool pos   = (tr == (rl ? ct.y : ct.x));
                        bool small = (sq < M2F);
                        rightw += (pos == small) ? uw : 0u;
                        if (pos) {
                            if (sq > LO2F) pl += (float)uw * (sqrtf(sq) - LOF);
                        } else if (sq < HI2F) {
                            float d = sqrtf(fmaxf(sq, 0.0f));
                            ns += (float)uw * (HIF - d);
                            unsigned idx = atomicAdd(&g_m, uw);
                            g_buf[idx] = d;
                            if (uw == 2u) g_buf[idx + 1] = d;
                        }
                    }
                }
            }
        }
    }

    // block reduce -> global atomics
#pragma unroll
    for (int o = 16; o; o >>= 1) {
        pl     += __shfl_down_sync(0xffffffffu, pl, o);
        ns     += __shfl_down_sync(0xffffffffu, ns, o);
        rightw += __shfl_down_sync(0xffffffffu, rightw, o);
    }
    float*    rpl = (float*)(smem + SM_RED);
    float*    rns = (float*)(smem + SM_RED + 32);
    unsigned* rrt = (unsigned*)(smem + SM_RED + 64);
    if (lane == 0) { rpl[wid] = pl; rns[wid] = ns; rrt[wid] = rightw; }
    __syncthreads();
    if (tid == 0) {
        float plb = 0.0f, nsb = 0.0f; unsigned rb = 0u;
#pragma unroll
        for (int w = 0; w < 8; ++w) { plb += rpl[w]; nsb += rns[w]; rb += rrt[w]; }
        atomicAdd(&g_pos_loss, (double)plb);
        atomicAdd(&g_negsum, (double)nsb);
        atomicAdd(&g_right, rb);
    }

    // ---------------- last-block finalize ----------------
    __shared__ unsigned s_last;
    if (tid == 0) {
        __threadfence();
        unsigned prev = atomicAdd(&g_done, 1u);
        s_last = (prev == NTOT - 1) ? 1u : 0u;
    }
    __syncthreads();
    if (!s_last) return;

    unsigned* hist = (unsigned*)(smem + SM_TILE);   // reuse tile smem
    __shared__ unsigned sh_b0, sh_b1, sh_b2, sh_r;
    __shared__ double   rsm[8];
    __shared__ double   sh_negloss;

    const unsigned k = atomicAdd(&g_k, 0u);
    const unsigned m = atomicAdd(&g_m, 0u);
    const int nt = 256;
    double negloss;

    if (m > k) {
        for (int bb = tid; bb < 2048; bb += nt) hist[bb] = 0u;
        __syncthreads();
        for (unsigned idx = tid; idx < m; idx += nt)
            atomicAdd(&hist[__float_as_uint(g_buf[idx]) >> 21], 1u);
        __syncthreads();
        if (tid == 0) {
            unsigned r = k; int bb = 0;
            for (; bb < 2048; ++bb) { if (r < hist[bb]) break; r -= hist[bb]; }
            sh_b0 = (unsigned)bb; sh_r = r;
        }
        __syncthreads();
        unsigned b0 = sh_b0;
        for (int bb = tid; bb < 2048; bb += nt) hist[bb] = 0u;
        __syncthreads();
        for (unsigned idx = tid; idx < m; idx += nt) {
            unsigned key = __float_as_uint(g_buf[idx]);
            if ((key >> 21) == b0) atomicAdd(&hist[(key >> 10) & 2047u], 1u);
        }
        __syncthreads();
        if (tid == 0) {
            unsigned r = sh_r; int bb = 0;
            for (; bb < 2048; ++bb) { if (r < hist[bb]) break; r -= hist[bb]; }
            sh_b1 = (unsigned)bb; sh_r = r;
        }
        __syncthreads();
        unsigned pref = (b0 << 11) | sh_b1;
        for (int bb = tid; bb < 1024; bb += nt) hist[bb] = 0u;
        __syncthreads();
        for (unsigned idx = tid; idx < m; idx += nt) {
            unsigned key = __float_as_uint(g_buf[idx]);
            if ((key >> 10) == pref) atomicAdd(&hist[key & 1023u], 1u);
        }
        __syncthreads();
        if (tid == 0) {
            unsigned r = sh_r; int bb = 0;
            for (; bb < 1024; ++bb) { if (r < hist[bb]) break; r -= hist[bb]; }
            sh_b2 = (unsigned)bb;
        }
        __syncthreads();
        unsigned thr_key = (sh_b0 << 21) | (sh_b1 << 10) | sh_b2;
        double a2 = 0.0;
        for (unsigned idx = tid; idx < m; idx += nt) {
            float v = g_buf[idx];
            if (__float_as_uint(v) < thr_key) a2 += (double)(HIF - v);
        }
#pragma unroll
        for (int o = 16; o; o >>= 1) a2 += __shfl_down_sync(0xffffffffu, a2, o);
        if (lane == 0) rsm[wid] = a2;
        __syncthreads();
        if (tid == 0) {
            double s = 0.0;
            for (int w = 0; w < 8; ++w) s += rsm[w];
            sh_negloss = s;
        }
        __syncthreads();
        negloss = sh_negloss;
    } else {
        negloss = g_negsum;
    }

    if (tid == 0) {
        double loss = (g_pos_loss + negloss) / (2.0 * (double)k);
        double accy = (double)atomicAdd(&g_right, 0u) / ((double)BN * (double)BN);
        out[0] = (float)loss;
        if (out_size > 1) out[1] = (float)accy;
    }
}

// ======================= launch ========================================
extern "C" void kernel_launch(void* const* d_in, const int* in_sizes, int n_in,
                              void* d_out, int out_size) {
    (void)in_sizes; (void)n_in;
    const float* X   = (const float*)d_in[0];
    const int*   tgt = (const int*)d_in[1];
    float*       out = (float*)d_out;

    cudaFuncSetAttribute(gemm_stats_kernel,
                         cudaFuncAttributeMaxDynamicSharedMemorySize, SM_TOTAL);

    prep_kernel<<<BN / 8 + 1, 256>>>(X, tgt);
    gemm_stats_kernel<<<NTOT, 256, SM_TOTAL>>>(tgt, out, out_size);
}